// round 3
// baseline (speedup 1.0000x reference)
#include <cuda_runtime.h>

#define THREADS 256

// --- fast transcendentals on the MUFU pipe (separate from FMA pipe) ---
__device__ __forceinline__ float softplus_fast(float x) {
    // softplus(x) = max(x,0) + ln(1 + exp(-|x|)); arg of ex2 is <= 0 so no overflow.
    float e, l;
    float y = fabsf(x) * -1.4426950408889634f;
    asm("ex2.approx.f32 %0, %1;" : "=f"(e) : "f"(y));
    float u = 1.0f + e;                 // u in (1, 2]
    asm("lg2.approx.f32 %0, %1;" : "=f"(l) : "f"(u));
    return fmaxf(x, 0.0f) + l * 0.6931471805599453f;
}

__device__ __forceinline__ float exp_fast(float x) {
    float e;
    asm("ex2.approx.f32 %0, %1;" : "=f"(e) : "f"(x * 1.4426950408889634f));
    return e;
}

__device__ __forceinline__ float rcp_fast(float x) {
    float r;
    asm("rcp.approx.f32 %0, %1;" : "=f"(r) : "f"(x));
    return r;
}

// SMEM layout (floats):
//   [0, 9216)        Ws  (16 x 24 x 24)
//   [9216, 9288)     W_out (24 x 3)
//   [9288, 9291)     b_out (3)
//   [9296, 9296+256*27) x staging block
#define SM_WS    0
#define SM_WOUT  9216
#define SM_BOUT  9288
#define SM_X     9296
#define SM_FLOATS (SM_X + THREADS * 27)

__global__ __launch_bounds__(THREADS)
void reslogit_kernel(const float* __restrict__ x,
                     const float* __restrict__ asc_train,
                     const float* __restrict__ asc_sm,
                     const float* __restrict__ asc_car,
                     const float* __restrict__ b_time,
                     const float* __restrict__ b_cost,
                     const float* __restrict__ Ws,
                     const float* __restrict__ W_out,
                     const float* __restrict__ b_out,
                     float* __restrict__ out,
                     int B)
{
    extern __shared__ float smem[];
    float* sW    = smem + SM_WS;
    float* sWout = smem + SM_WOUT;
    float* sbout = smem + SM_BOUT;
    float* sx    = smem + SM_X;

    const int tid  = threadIdx.x;
    const int row0 = blockIdx.x * THREADS;

    // cooperative load of Ws as float4 (9216 floats = 2304 float4; 2304 % THREADS == 0)
    {
        const float4* Ws4 = reinterpret_cast<const float4*>(Ws);
        float4* sW4 = reinterpret_cast<float4*>(sW);
        #pragma unroll
        for (int i = 0; i < 2304 / THREADS; i++)
            sW4[tid + i * THREADS] = Ws4[tid + i * THREADS];
    }
    if (tid < 72) sWout[tid] = W_out[tid];
    if (tid < 3)  sbout[tid] = b_out[tid];

    // cooperative, coalesced load of this block's x rows
    {
        const float* xblk = x + (size_t)row0 * 27;
        int nrow  = B - row0; if (nrow > THREADS) nrow = THREADS;
        int nelem = nrow * 27;
        for (int i = tid; i < nelem; i += THREADS) sx[i] = xblk[i];
    }
    __syncthreads();

    const int row = row0 + tid;
    if (row >= B) return;

    // Scalar params kept live across the whole kernel (5 regs).
    const float bt = *b_time, bc = *b_cost;
    const float a1 = *asc_train, a2 = *asc_sm, a3 = *asc_car;

    // Build V into the scan state `ov`. The scan (faithful to the reference):
    //   S_k   = S_{k-1} + softplus(ov_{k-1} @ W_k)
    //   ov_k  = ov_{k-1} - S_k          (running sum, not the increment!)
    // and the residual block's output is V - S_16 (recomputed from SMEM at the end).
    float ov[24], S[24];
    const float* xr = sx + tid * 27;   // stride 27 is coprime with 32 banks: conflict-free
    #pragma unroll
    for (int j = 0; j < 19; j++) ov[j] = xr[j];
    ov[19] = xr[21];
    ov[20] = xr[24];
    ov[21] = fmaf(bc, xr[20], fmaf(bt, xr[19], a1));
    ov[22] = fmaf(bc, xr[23], fmaf(bt, xr[22], a2));
    ov[23] = fmaf(bc, xr[26], fmaf(bt, xr[25], a3));
    #pragma unroll
    for (int j = 0; j < 24; j++) S[j] = 0.0f;

    // 16-step scan; k-loop NOT unrolled (keeps body small, inside I$)
    #pragma unroll 1
    for (int k = 0; k < 16; k++) {
        const float* Wk = sW + k * 576;
        float acc[24];
        #pragma unroll
        for (int j = 0; j < 24; j++) acc[j] = 0.0f;
        #pragma unroll
        for (int i = 0; i < 24; i++) {
            const float o = ov[i];
            #pragma unroll
            for (int j = 0; j < 24; j++)
                acc[j] = fmaf(o, Wk[i * 24 + j], acc[j]);   // broadcast LDS.128
        }
        #pragma unroll
        for (int j = 0; j < 24; j++) {
            S[j]  += softplus_fast(acc[j]);
            ov[j] -= S[j];
        }
    }

    // U1 = V - S_16; recompute V from the x row still in SMEM.
    float u[24];
    #pragma unroll
    for (int j = 0; j < 19; j++) u[j] = xr[j] - S[j];
    u[19] = xr[21] - S[19];
    u[20] = xr[24] - S[20];
    u[21] = fmaf(bc, xr[20], fmaf(bt, xr[19], a1)) - S[21];
    u[22] = fmaf(bc, xr[23], fmaf(bt, xr[22], a2)) - S[22];
    u[23] = fmaf(bc, xr[26], fmaf(bt, xr[25], a3)) - S[23];

    // softmax over 24 (shift by max for safety; mathematically identical)
    float m = u[0];
    #pragma unroll
    for (int j = 1; j < 24; j++) m = fmaxf(m, u[j]);

    float e[24];
    float sum = 0.0f;
    #pragma unroll
    for (int j = 0; j < 24; j++) {
        e[j] = exp_fast(u[j] - m);
        sum += e[j];
    }
    const float inv = rcp_fast(sum);

    float d0 = 0.0f, d1 = 0.0f, d2 = 0.0f;
    #pragma unroll
    for (int j = 0; j < 24; j++) {
        const float ej = e[j];
        d0 = fmaf(ej, sWout[j * 3 + 0], d0);
        d1 = fmaf(ej, sWout[j * 3 + 1], d1);
        d2 = fmaf(ej, sWout[j * 3 + 2], d2);
    }
    const float o0 = fmaxf(fmaf(d0, inv, sbout[0]), 0.0f);
    const float o1 = fmaxf(fmaf(d1, inv, sbout[1]), 0.0f);
    const float o2 = fmaxf(fmaf(d2, inv, sbout[2]), 0.0f);

    float* op = out + (size_t)row * 3;
    op[0] = o0; op[1] = o1; op[2] = o2;
}

extern "C" void kernel_launch(void* const* d_in, const int* in_sizes, int n_in,
                              void* d_out, int out_size)
{
    const float* x         = (const float*)d_in[0];
    const float* asc_train = (const float*)d_in[1];
    const float* asc_sm    = (const float*)d_in[2];
    const float* asc_car   = (const float*)d_in[3];
    const float* b_time    = (const float*)d_in[4];
    const float* b_cost    = (const float*)d_in[5];
    const float* Ws        = (const float*)d_in[6];
    const float* W_out     = (const float*)d_in[7];
    const float* b_out     = (const float*)d_in[8];
    float* out = (float*)d_out;

    const int B = in_sizes[0] / 27;
    const int smem_bytes = SM_FLOATS * sizeof(float);

    cudaFuncSetAttribute(reslogit_kernel,
                         cudaFuncAttributeMaxDynamicSharedMemorySize, smem_bytes);

    const int grid = (B + THREADS - 1) / THREADS;
    reslogit_kernel<<<grid, THREADS, smem_bytes>>>(
        x, asc_train, asc_sm, asc_car, b_time, b_cost, Ws, W_out, b_out, out, B);
}

// round 4
// speedup vs baseline: 1.1305x; 1.1305x over previous
#include <cuda_runtime.h>
#include <cstdint>

#define THREADS 256
#define ROWS_PER_THREAD 2
#define ROWS_PER_BLOCK (THREADS * ROWS_PER_THREAD)   // 512

// --- packed f32x2 FMA (Blackwell FFMA2): two independent rn-FMAs, one issue slot ---
#define FMA2(d, a, b) asm("fma.rn.f32x2 %0, %1, %2, %0;" : "+l"(d) : "l"(a), "l"(b))
#define PACK2(d, s)   asm("mov.b64 %0, {%1, %1};" : "=l"(d) : "r"(s))
#define UNPACK2(lo, hi, d) asm("mov.b64 {%0, %1}, %2;" : "=r"(lo), "=r"(hi) : "l"(d))

// --- fast transcendentals on the MUFU pipe (separate from FMA pipe) ---
__device__ __forceinline__ float softplus_fast(float x) {
    // softplus(x) = max(x,0) + ln(1 + exp(-|x|)); arg of ex2 is <= 0 so no overflow.
    float e, l;
    float y = fabsf(x) * -1.4426950408889634f;
    asm("ex2.approx.f32 %0, %1;" : "=f"(e) : "f"(y));
    float u = 1.0f + e;                 // u in (1, 2]
    asm("lg2.approx.f32 %0, %1;" : "=f"(l) : "f"(u));
    return fmaxf(x, 0.0f) + l * 0.6931471805599453f;
}

__device__ __forceinline__ float exp_fast(float x) {
    float e;
    asm("ex2.approx.f32 %0, %1;" : "=f"(e) : "f"(x * 1.4426950408889634f));
    return e;
}

__device__ __forceinline__ float rcp_fast(float x) {
    float r;
    asm("rcp.approx.f32 %0, %1;" : "=f"(r) : "f"(x));
    return r;
}

// SMEM layout (floats):
//   [0, 9216)        Ws  (16 x 24 x 24)
//   [9216, 9288)     W_out (24 x 3)
//   [9288, 9291)     b_out (3)
//   [9296, ...)      x staging: 512 rows x 27
#define SM_WS    0
#define SM_WOUT  9216
#define SM_BOUT  9288
#define SM_X     9296
#define SM_FLOATS (SM_X + ROWS_PER_BLOCK * 27)

// Epilogue for one row: U1 = V - S, softmax, @W_out + b_out, relu, store.
__device__ __forceinline__ void epilogue_row(
    const float* __restrict__ xr, const float* __restrict__ S,
    const float* __restrict__ sWout, const float* __restrict__ sbout,
    float bt, float bc, float a1, float a2, float a3,
    float* __restrict__ op)
{
    float u[24];
    #pragma unroll
    for (int j = 0; j < 19; j++) u[j] = xr[j] - S[j];
    u[19] = xr[21] - S[19];
    u[20] = xr[24] - S[20];
    u[21] = fmaf(bc, xr[20], fmaf(bt, xr[19], a1)) - S[21];
    u[22] = fmaf(bc, xr[23], fmaf(bt, xr[22], a2)) - S[22];
    u[23] = fmaf(bc, xr[26], fmaf(bt, xr[25], a3)) - S[23];

    float m = u[0];
    #pragma unroll
    for (int j = 1; j < 24; j++) m = fmaxf(m, u[j]);

    float e[24];
    float sum = 0.0f;
    #pragma unroll
    for (int j = 0; j < 24; j++) {
        e[j] = exp_fast(u[j] - m);
        sum += e[j];
    }
    const float inv = rcp_fast(sum);

    float d0 = 0.0f, d1 = 0.0f, d2 = 0.0f;
    #pragma unroll
    for (int j = 0; j < 24; j++) {
        const float ej = e[j];
        d0 = fmaf(ej, sWout[j * 3 + 0], d0);
        d1 = fmaf(ej, sWout[j * 3 + 1], d1);
        d2 = fmaf(ej, sWout[j * 3 + 2], d2);
    }
    op[0] = fmaxf(fmaf(d0, inv, sbout[0]), 0.0f);
    op[1] = fmaxf(fmaf(d1, inv, sbout[1]), 0.0f);
    op[2] = fmaxf(fmaf(d2, inv, sbout[2]), 0.0f);
}

__global__ __launch_bounds__(THREADS, 1)
void reslogit_kernel(const float* __restrict__ x,
                     const float* __restrict__ asc_train,
                     const float* __restrict__ asc_sm,
                     const float* __restrict__ asc_car,
                     const float* __restrict__ b_time,
                     const float* __restrict__ b_cost,
                     const float* __restrict__ Ws,
                     const float* __restrict__ W_out,
                     const float* __restrict__ b_out,
                     float* __restrict__ out,
                     int B)
{
    extern __shared__ float smem[];
    float* sW    = smem + SM_WS;
    float* sWout = smem + SM_WOUT;
    float* sbout = smem + SM_BOUT;
    float* sx    = smem + SM_X;

    const int tid  = threadIdx.x;
    const int row0 = blockIdx.x * ROWS_PER_BLOCK;

    // cooperative load of Ws as float4 (9216 floats = 2304 float4; 2304 % THREADS == 0)
    {
        const float4* Ws4 = reinterpret_cast<const float4*>(Ws);
        float4* sW4 = reinterpret_cast<float4*>(sW);
        #pragma unroll
        for (int i = 0; i < 2304 / THREADS; i++)
            sW4[tid + i * THREADS] = Ws4[tid + i * THREADS];
    }
    if (tid < 72) sWout[tid] = W_out[tid];
    if (tid < 3)  sbout[tid] = b_out[tid];

    // cooperative, coalesced load of this block's x rows (512 x 27)
    {
        const float* xblk = x + (size_t)row0 * 27;
        int nrow  = B - row0; if (nrow > ROWS_PER_BLOCK) nrow = ROWS_PER_BLOCK;
        int nelem = nrow * 27;
        for (int i = tid; i < nelem; i += THREADS) sx[i] = xblk[i];
    }
    __syncthreads();

    const int rowA = row0 + tid;            // first row for this thread
    const int rowB = rowA + THREADS;        // second row
    const bool hasA = rowA < B, hasB = rowB < B;
    if (!hasA) return;

    const float bt = *b_time, bc = *b_cost;
    const float a1 = *asc_train, a2 = *asc_sm, a3 = *asc_car;

    // Build V for both rows. x rows at stride 27 (coprime with 32 banks).
    const float* xrA = sx + tid * 27;
    const float* xrB = sx + (tid + THREADS) * 27;

    float ovA[24], ovB[24], SA[24], SB[24];
    #pragma unroll
    for (int j = 0; j < 19; j++) { ovA[j] = xrA[j]; ovB[j] = xrB[j]; }
    ovA[19] = xrA[21]; ovB[19] = xrB[21];
    ovA[20] = xrA[24]; ovB[20] = xrB[24];
    ovA[21] = fmaf(bc, xrA[20], fmaf(bt, xrA[19], a1));
    ovB[21] = fmaf(bc, xrB[20], fmaf(bt, xrB[19], a1));
    ovA[22] = fmaf(bc, xrA[23], fmaf(bt, xrA[22], a2));
    ovB[22] = fmaf(bc, xrB[23], fmaf(bt, xrB[22], a2));
    ovA[23] = fmaf(bc, xrA[26], fmaf(bt, xrA[25], a3));
    ovB[23] = fmaf(bc, xrB[26], fmaf(bt, xrB[25], a3));
    #pragma unroll
    for (int j = 0; j < 24; j++) { SA[j] = 0.0f; SB[j] = 0.0f; }

    // 16-step scan; each W row (24 floats = 6 LDS.128) loaded ONCE, used for
    // both rows, consumed by packed FFMA2 (lanes = adjacent j-columns).
    #pragma unroll 1
    for (int k = 0; k < 16; k++) {
        const double2* Wk2 = reinterpret_cast<const double2*>(sW + k * 576);

        uint64_t accA[12], accB[12];
        #pragma unroll
        for (int p = 0; p < 12; p++) { accA[p] = 0ull; accB[p] = 0ull; }

        #pragma unroll
        for (int i = 0; i < 24; i++) {
            // 6x LDS.128; each double2 holds two f32x2 j-pairs
            const double2 w0 = Wk2[i * 6 + 0];
            const double2 w1 = Wk2[i * 6 + 1];
            const double2 w2 = Wk2[i * 6 + 2];
            const double2 w3 = Wk2[i * 6 + 3];
            const double2 w4 = Wk2[i * 6 + 4];
            const double2 w5 = Wk2[i * 6 + 5];
            const uint64_t* w = reinterpret_cast<const uint64_t*>(&w0); // w[0..11] contiguous? no — use explicit
            (void)w;
            uint64_t wp[12];
            wp[0]  = *reinterpret_cast<const uint64_t*>(&w0.x);
            wp[1]  = *reinterpret_cast<const uint64_t*>(&w0.y);
            wp[2]  = *reinterpret_cast<const uint64_t*>(&w1.x);
            wp[3]  = *reinterpret_cast<const uint64_t*>(&w1.y);
            wp[4]  = *reinterpret_cast<const uint64_t*>(&w2.x);
            wp[5]  = *reinterpret_cast<const uint64_t*>(&w2.y);
            wp[6]  = *reinterpret_cast<const uint64_t*>(&w3.x);
            wp[7]  = *reinterpret_cast<const uint64_t*>(&w3.y);
            wp[8]  = *reinterpret_cast<const uint64_t*>(&w4.x);
            wp[9]  = *reinterpret_cast<const uint64_t*>(&w4.y);
            wp[10] = *reinterpret_cast<const uint64_t*>(&w5.x);
            wp[11] = *reinterpret_cast<const uint64_t*>(&w5.y);

            uint64_t ooA, ooB;
            PACK2(ooA, __float_as_uint(ovA[i]));
            PACK2(ooB, __float_as_uint(ovB[i]));

            #pragma unroll
            for (int p = 0; p < 12; p++) {
                FMA2(accA[p], ooA, wp[p]);
                FMA2(accB[p], ooB, wp[p]);
            }
        }

        // unpack, softplus (MUFU), scan update for both rows
        #pragma unroll
        for (int p = 0; p < 12; p++) {
            uint32_t lo, hi;
            UNPACK2(lo, hi, accA[p]);
            SA[2*p]   += softplus_fast(__uint_as_float(lo));
            SA[2*p+1] += softplus_fast(__uint_as_float(hi));
            ovA[2*p]   -= SA[2*p];
            ovA[2*p+1] -= SA[2*p+1];
            UNPACK2(lo, hi, accB[p]);
            SB[2*p]   += softplus_fast(__uint_as_float(lo));
            SB[2*p+1] += softplus_fast(__uint_as_float(hi));
            ovB[2*p]   -= SB[2*p];
            ovB[2*p+1] -= SB[2*p+1];
        }
    }

    epilogue_row(xrA, SA, sWout, sbout, bt, bc, a1, a2, a3, out + (size_t)rowA * 3);
    if (hasB)
        epilogue_row(xrB, SB, sWout, sbout, bt, bc, a1, a2, a3, out + (size_t)rowB * 3);
}

extern "C" void kernel_launch(void* const* d_in, const int* in_sizes, int n_in,
                              void* d_out, int out_size)
{
    const float* x         = (const float*)d_in[0];
    const float* asc_train = (const float*)d_in[1];
    const float* asc_sm    = (const float*)d_in[2];
    const float* asc_car   = (const float*)d_in[3];
    const float* b_time    = (const float*)d_in[4];
    const float* b_cost    = (const float*)d_in[5];
    const float* Ws        = (const float*)d_in[6];
    const float* W_out     = (const float*)d_in[7];
    const float* b_out     = (const float*)d_in[8];
    float* out = (float*)d_out;

    const int B = in_sizes[0] / 27;
    const int smem_bytes = SM_FLOATS * sizeof(float);

    cudaFuncSetAttribute(reslogit_kernel,
                         cudaFuncAttributeMaxDynamicSharedMemorySize, smem_bytes);

    const int grid = (B + ROWS_PER_BLOCK - 1) / ROWS_PER_BLOCK;
    reslogit_kernel<<<grid, THREADS, smem_bytes>>>(
        x, asc_train, asc_sm, asc_car, b_time, b_cost, Ws, W_out, b_out, out, B);
}